// round 3
// baseline (speedup 1.0000x reference)
#include <cuda_runtime.h>
#include <cuda_bf16.h>
#include <math.h>

// ---------------------------------------------------------------------------
// Problem constants (B=1, S=4096, DIM=1536, HEADS=12, HEAD_DIM=128)
// ---------------------------------------------------------------------------
#define SEQ    4096
#define DIM    1536
#define NHEADS 12
#define HDIM   128
#define EPS    1e-6f

// Scratch (allocation-free rule: __device__ globals)
__device__ float g_q[SEQ * DIM];
__device__ float g_k[SEQ * DIM];
__device__ float g_v[SEQ * DIM];
__device__ float g_attn[SEQ * DIM];
__device__ float g_xt[SEQ * DIM];          // tf32-rounded x
__device__ float g_wq[DIM * DIM];          // tf32-rounded weights
__device__ float g_wk[DIM * DIM];
__device__ float g_wv[DIM * DIM];
__device__ float g_wo[DIM * DIM];
__device__ float g_trig[SEQ * 64 * 2];     // interleaved cos, sin per (pos, pair)

// ---------------------------------------------------------------------------
// Helpers
// ---------------------------------------------------------------------------
__device__ __forceinline__ float to_tf32(float x) {
    unsigned u;
    asm("cvt.rna.tf32.f32 %0, %1;" : "=r"(u) : "f"(x));
    return __uint_as_float(u);
}
__device__ __forceinline__ unsigned fu(float x) { return __float_as_uint(x); }

__device__ __forceinline__ void mma_tf32(float* d, const unsigned* a,
                                         unsigned b0, unsigned b1) {
    asm volatile(
        "mma.sync.aligned.m16n8k8.row.col.f32.tf32.tf32.f32 "
        "{%0,%1,%2,%3}, {%4,%5,%6,%7}, {%8,%9}, {%0,%1,%2,%3};\n"
        : "+f"(d[0]), "+f"(d[1]), "+f"(d[2]), "+f"(d[3])
        : "r"(a[0]), "r"(a[1]), "r"(a[2]), "r"(a[3]), "r"(b0), "r"(b1));
}

__device__ __forceinline__ void cp16(float* smem_dst, const float* gsrc) {
    unsigned s = (unsigned)__cvta_generic_to_shared(smem_dst);
    asm volatile("cp.async.cg.shared.global [%0], [%1], 16;\n" :: "r"(s), "l"(gsrc));
}
__device__ __forceinline__ void cp_commit() {
    asm volatile("cp.async.commit_group;\n");
}
template <int N>
__device__ __forceinline__ void cp_wait() {
    asm volatile("cp.async.wait_group %0;\n" :: "n"(N));
}

// ---------------------------------------------------------------------------
// Prep: tf32-round a buffer (vectorized)
// ---------------------------------------------------------------------------
__global__ __launch_bounds__(256) void round_tf32_kernel(
    const float* __restrict__ src, float* __restrict__ dst, int n4)
{
    int i = blockIdx.x * blockDim.x + threadIdx.x;
    if (i >= n4) return;
    float4 v = ((const float4*)src)[i];
    ((float4*)dst)[i] = make_float4(to_tf32(v.x), to_tf32(v.y),
                                    to_tf32(v.z), to_tf32(v.w));
}

// ---------------------------------------------------------------------------
// RoPE trig table with double-precision range reduction.
// ---------------------------------------------------------------------------
__global__ __launch_bounds__(256) void trig_kernel(const float* __restrict__ freqs) {
    int idx = blockIdx.x * blockDim.x + threadIdx.x;
    if (idx >= SEQ * 64) return;
    double a = (double)freqs[idx];
    double s, c;
    sincos(a, &s, &c);
    g_trig[idx * 2 + 0] = (float)c;
    g_trig[idx * 2 + 1] = (float)s;
}

// ---------------------------------------------------------------------------
// tf32 tensor-core GEMM with cp.async 3-stage pipeline.
// C[M,N] = A[M,K] @ W[N,K]^T + bias[N].  A, W pre-rounded to tf32.
// BM=BN=128, BK=16, 256 threads (8 warps 4m x 2n), warp tile 32x64.
// ROUND: tf32-round the output (for v).
// ---------------------------------------------------------------------------
#define GBK      16
#define GSTRIDE  20
#define GSTG     3
#define GEMM_SMEM_BYTES (GSTG * 2 * 128 * GSTRIDE * 4)   // 61440

template <bool ROUND>
__global__ __launch_bounds__(256, 2) void gemm_tf32_kernel(
    const float* __restrict__ A, const float* __restrict__ W,
    const float* __restrict__ bias, float* __restrict__ C,
    int M, int N, int K)
{
    extern __shared__ float smem[];
    // per stage: A 128*20, W 128*20
    const int t    = threadIdx.x;
    const int lane = t & 31;
    const int warp = t >> 5;
    const int wm   = warp >> 1;
    const int wn   = warp & 1;
    const int bm   = blockIdx.y * 128;
    const int bn   = blockIdx.x * 128;

    const int lrow = t >> 2;        // 0..63
    const int lc4  = (t & 3) * 4;   // 0,4,8,12

    const float* Ap = A + (size_t)(bm + lrow) * K + lc4;
    const float* Wp = W + (size_t)(bn + lrow) * K + lc4;
    const size_t rK = (size_t)64 * K;

    const int KITERS = K / GBK;     // 96

    // stage loader
    auto stage = [&](int it) {
        float* as = smem + (it % GSTG) * (2 * 128 * GSTRIDE);
        float* ws = as + 128 * GSTRIDE;
        const float* ap = Ap + it * GBK;
        const float* wp = Wp + it * GBK;
        cp16(&as[lrow * GSTRIDE + lc4],        ap);
        cp16(&as[(lrow + 64) * GSTRIDE + lc4], ap + rK);
        cp16(&ws[lrow * GSTRIDE + lc4],        wp);
        cp16(&ws[(lrow + 64) * GSTRIDE + lc4], wp + rK);
        cp_commit();
    };

    float c[2][8][4];
#pragma unroll
    for (int mt = 0; mt < 2; mt++)
#pragma unroll
        for (int nt = 0; nt < 8; nt++)
#pragma unroll
            for (int j = 0; j < 4; j++) c[mt][nt][j] = 0.f;

    stage(0);
    stage(1);

    const int r_a = wm * 32 + (lane >> 2);
    const int r_b = wn * 64 + (lane >> 2);
    const int kq  = lane & 3;

    for (int it = 0; it < KITERS; ++it) {
        if (it + 1 < KITERS) cp_wait<1>(); else cp_wait<0>();
        __syncthreads();
        if (it + 2 < KITERS) stage(it + 2);

        const float* as = smem + (it % GSTG) * (2 * 128 * GSTRIDE);
        const float* ws = as + 128 * GSTRIDE;

#pragma unroll
        for (int kt = 0; kt < 2; ++kt) {
            const int kc = kt * 8 + kq;
            unsigned a[2][4];
#pragma unroll
            for (int mt = 0; mt < 2; ++mt) {
                int r = r_a + mt * 16;
                a[mt][0] = fu(as[r * GSTRIDE + kc]);
                a[mt][1] = fu(as[(r + 8) * GSTRIDE + kc]);
                a[mt][2] = fu(as[r * GSTRIDE + kc + 4]);
                a[mt][3] = fu(as[(r + 8) * GSTRIDE + kc + 4]);
            }
#pragma unroll
            for (int nt = 0; nt < 8; ++nt) {
                int n = r_b + nt * 8;
                unsigned b0 = fu(ws[n * GSTRIDE + kc]);
                unsigned b1 = fu(ws[n * GSTRIDE + kc + 4]);
                mma_tf32(c[0][nt], a[0], b0, b1);
                mma_tf32(c[1][nt], a[1], b0, b1);
            }
        }
        __syncthreads();
    }

    // Epilogue: bias + (optional tf32 round) + store
#pragma unroll
    for (int mt = 0; mt < 2; ++mt) {
#pragma unroll
        for (int nt = 0; nt < 8; ++nt) {
            int r0  = bm + wm * 32 + mt * 16 + (lane >> 2);
            int col = bn + wn * 64 + nt * 8 + 2 * (lane & 3);
            float bb0 = bias[col], bb1 = bias[col + 1];
            float v0 = c[mt][nt][0] + bb0, v1 = c[mt][nt][1] + bb1;
            float v2 = c[mt][nt][2] + bb0, v3 = c[mt][nt][3] + bb1;
            if (ROUND) {
                v0 = to_tf32(v0); v1 = to_tf32(v1);
                v2 = to_tf32(v2); v3 = to_tf32(v3);
            }
            *(float2*)&C[(size_t)r0 * N + col]       = make_float2(v0, v1);
            *(float2*)&C[(size_t)(r0 + 8) * N + col] = make_float2(v2, v3);
        }
    }
}

// ---------------------------------------------------------------------------
// Fused RMSNorm + RoPE, in-place; output tf32-rounded. One block per position.
// ---------------------------------------------------------------------------
__global__ __launch_bounds__(256) void rmsnorm_rope_kernel(
    float* __restrict__ X, const float* __restrict__ g)
{
    __shared__ float sh[DIM];
    __shared__ float red[8];
    __shared__ float s_r;

    const int s = blockIdx.x;
    const int t = threadIdx.x;
    float* row = X + (size_t)s * DIM;

    float ss = 0.f;
    for (int i = t; i < DIM; i += 256) {
        float v = row[i];
        sh[i] = v;
        ss += v * v;
    }
#pragma unroll
    for (int off = 16; off > 0; off >>= 1)
        ss += __shfl_xor_sync(0xFFFFFFFFu, ss, off);
    if ((t & 31) == 0) red[t >> 5] = ss;
    __syncthreads();
    if (t == 0) {
        float tot = 0.f;
#pragma unroll
        for (int w = 0; w < 8; w++) tot += red[w];
        s_r = rsqrtf(tot / (float)DIM + EPS);
    }
    __syncthreads();
    const float r = s_r;

    for (int p = t; p < DIM / 2; p += 256) {
        int f0 = 2 * p, f1 = 2 * p + 1;
        int j = p & 63;
        float c  = g_trig[((size_t)s * 64 + j) * 2 + 0];
        float sn = g_trig[((size_t)s * 64 + j) * 2 + 1];
        float v0 = sh[f0] * r * g[f0];
        float v1 = sh[f1] * r * g[f1];
        row[f0] = to_tf32(v0 * c - v1 * sn);
        row[f1] = to_tf32(v0 * sn + v1 * c);
    }
}

// ---------------------------------------------------------------------------
// tf32 flash attention with cp.async double-buffered K/V (BK=32).
// 128 threads (4 warps), BQ=64 (16 rows/warp). Inputs pre-rounded tf32.
// ---------------------------------------------------------------------------
#define FBK       32
#define KS_STRIDE 132
#define VS_STRIDE 136
#define PS_STRIDE 36
#define FA_SMEM_FLOATS (2 * FBK * KS_STRIDE + 2 * FBK * VS_STRIDE + 64 * PS_STRIDE)
#define FA_SMEM_BYTES  (FA_SMEM_FLOATS * 4)    // 77824

__global__ __launch_bounds__(128, 2) void flash_tf32_kernel(
    const float* __restrict__ Q, const float* __restrict__ Kg,
    const float* __restrict__ Vg, float* __restrict__ O)
{
    extern __shared__ float sm[];
    float* Kb[2];
    float* Vb[2];
    Kb[0] = sm;
    Kb[1] = Kb[0] + FBK * KS_STRIDE;
    Vb[0] = Kb[1] + FBK * KS_STRIDE;
    Vb[1] = Vb[0] + FBK * VS_STRIDE;
    float* Ps = Vb[1] + FBK * VS_STRIDE;

    const int h    = blockIdx.y;
    const int qb   = blockIdx.x;
    const int t    = threadIdx.x;
    const int lane = t & 31;
    const int warp = t >> 5;
    const int r0   = lane >> 2;
    const int qc   = lane & 3;
    const float scale = 0.08838834764831845f;   // 1/sqrt(128)

    // ---- Stage Q tile (rows 0..31 -> Kb[0], 32..63 -> Kb[1]) ----
    {
        const float* src = Q + (size_t)(qb * 64) * DIM + h * HDIM;
        for (int i = t; i < 64 * 32; i += 128) {
            int r = i >> 5, c4 = (i & 31) * 4;
            float4 v = *(const float4*)&src[(size_t)r * DIM + c4];
            float* d = Kb[r >> 5] + (r & 31) * KS_STRIDE + c4;
            *(float4*)d = v;
        }
    }
    __syncthreads();

    unsigned qa[16][4];
    {
        const float* qbuf = Kb[warp >> 1];
        const int rb = (warp * 16 + r0) & 31;
#pragma unroll
        for (int kt = 0; kt < 16; ++kt) {
            int kc = kt * 8 + qc;
            qa[kt][0] = fu(qbuf[rb * KS_STRIDE + kc]);
            qa[kt][1] = fu(qbuf[(rb + 8) * KS_STRIDE + kc]);
            qa[kt][2] = fu(qbuf[rb * KS_STRIDE + kc + 4]);
            qa[kt][3] = fu(qbuf[(rb + 8) * KS_STRIDE + kc + 4]);
        }
    }
    __syncthreads();

    // ---- cp.async stage helper: K/V tile kb into buffer kb&1 ----
    auto stage_kv = [&](int kb) {
        float* dk = Kb[kb & 1];
        float* dv = Vb[kb & 1];
        const float* ks = Kg + (size_t)(kb * FBK) * DIM + h * HDIM;
        const float* vs = Vg + (size_t)(kb * FBK) * DIM + h * HDIM;
        for (int i = t; i < FBK * 32; i += 128) {
            int r = i >> 5, c4 = (i & 31) * 4;
            cp16(&dk[r * KS_STRIDE + c4], &ks[(size_t)r * DIM + c4]);
            cp16(&dv[r * VS_STRIDE + c4], &vs[(size_t)r * DIM + c4]);
        }
        cp_commit();
    };

    stage_kv(0);
    stage_kv(1);

    float o[16][4];
#pragma unroll
    for (int nt = 0; nt < 16; ++nt)
#pragma unroll
        for (int j = 0; j < 4; ++j) o[nt][j] = 0.f;

    float m0 = -1e30f, m1 = -1e30f, l0 = 0.f, l1 = 0.f;
    const int prow = warp * 16 + r0;
    const int NT = SEQ / FBK;   // 128

    for (int kb = 0; kb < NT; ++kb) {
        if (kb + 1 < NT) cp_wait<1>(); else cp_wait<0>();
        __syncthreads();

        const float* Ks = Kb[kb & 1];
        const float* Vs = Vb[kb & 1];

        // ---- S = Q @ K^T (per warp: 16 x 32) ----
        float s[4][4];
#pragma unroll
        for (int nt = 0; nt < 4; ++nt)
#pragma unroll
            for (int j = 0; j < 4; ++j) s[nt][j] = 0.f;

#pragma unroll
        for (int nt = 0; nt < 4; ++nt) {
            const int n = nt * 8 + r0;
#pragma unroll
            for (int kt = 0; kt < 16; ++kt) {
                int kc = kt * 8 + qc;
                unsigned b0 = fu(Ks[n * KS_STRIDE + kc]);
                unsigned b1 = fu(Ks[n * KS_STRIDE + kc + 4]);
                mma_tf32(s[nt], qa[kt], b0, b1);
            }
        }

        // ---- Online softmax ----
        float mx0 = -1e30f, mx1 = -1e30f;
#pragma unroll
        for (int nt = 0; nt < 4; ++nt) {
            mx0 = fmaxf(mx0, fmaxf(s[nt][0], s[nt][1]));
            mx1 = fmaxf(mx1, fmaxf(s[nt][2], s[nt][3]));
        }
        mx0 = fmaxf(mx0, __shfl_xor_sync(0xFFFFFFFFu, mx0, 1));
        mx0 = fmaxf(mx0, __shfl_xor_sync(0xFFFFFFFFu, mx0, 2));
        mx1 = fmaxf(mx1, __shfl_xor_sync(0xFFFFFFFFu, mx1, 1));
        mx1 = fmaxf(mx1, __shfl_xor_sync(0xFFFFFFFFu, mx1, 2));

        float nm0 = fmaxf(m0, mx0 * scale);
        float nm1 = fmaxf(m1, mx1 * scale);
        float corr0 = __expf(m0 - nm0);
        float corr1 = __expf(m1 - nm1);

        float sum0 = 0.f, sum1 = 0.f;
#pragma unroll
        for (int nt = 0; nt < 4; ++nt) {
            s[nt][0] = __expf(s[nt][0] * scale - nm0);
            s[nt][1] = __expf(s[nt][1] * scale - nm0);
            s[nt][2] = __expf(s[nt][2] * scale - nm1);
            s[nt][3] = __expf(s[nt][3] * scale - nm1);
            sum0 += s[nt][0] + s[nt][1];
            sum1 += s[nt][2] + s[nt][3];
        }
        sum0 += __shfl_xor_sync(0xFFFFFFFFu, sum0, 1);
        sum0 += __shfl_xor_sync(0xFFFFFFFFu, sum0, 2);
        sum1 += __shfl_xor_sync(0xFFFFFFFFu, sum1, 1);
        sum1 += __shfl_xor_sync(0xFFFFFFFFu, sum1, 2);

        l0 = l0 * corr0 + sum0;
        l1 = l1 * corr1 + sum1;
        m0 = nm0;
        m1 = nm1;

#pragma unroll
        for (int nt = 0; nt < 16; ++nt) {
            o[nt][0] *= corr0; o[nt][1] *= corr0;
            o[nt][2] *= corr1; o[nt][3] *= corr1;
        }

        // ---- P -> smem (warp-local rows), tf32-rounded ----
#pragma unroll
        for (int nt = 0; nt < 4; ++nt) {
            int pc = nt * 8 + 2 * qc;
            *(float2*)&Ps[prow * PS_STRIDE + pc] =
                make_float2(to_tf32(s[nt][0]), to_tf32(s[nt][1]));
            *(float2*)&Ps[(prow + 8) * PS_STRIDE + pc] =
                make_float2(to_tf32(s[nt][2]), to_tf32(s[nt][3]));
        }
        __syncwarp();

        // ---- O += P @ V ----
#pragma unroll
        for (int kt = 0; kt < 4; ++kt) {
            unsigned a[4];
            int kc = kt * 8 + qc;
            a[0] = fu(Ps[prow * PS_STRIDE + kc]);
            a[1] = fu(Ps[(prow + 8) * PS_STRIDE + kc]);
            a[2] = fu(Ps[prow * PS_STRIDE + kc + 4]);
            a[3] = fu(Ps[(prow + 8) * PS_STRIDE + kc + 4]);
            const int vr = kc * VS_STRIDE + r0;
#pragma unroll
            for (int nt = 0; nt < 16; ++nt) {
                unsigned b0 = fu(Vs[vr + nt * 8]);
                unsigned b1 = fu(Vs[vr + nt * 8 + 4 * VS_STRIDE]);
                mma_tf32(o[nt], a, b0, b1);
            }
        }
        __syncthreads();          // all warps done with this buffer
        if (kb + 2 < NT) stage_kv(kb + 2);
    }

    // ---- Epilogue: normalize, tf32-round (feeds O-proj GEMM), store ----
    float inv0 = 1.f / l0, inv1 = 1.f / l1;
    int grow = qb * 64 + warp * 16 + r0;
#pragma unroll
    for (int nt = 0; nt < 16; ++nt) {
        int col = h * HDIM + nt * 8 + 2 * qc;
        *(float2*)&O[(size_t)grow * DIM + col] =
            make_float2(to_tf32(o[nt][0] * inv0), to_tf32(o[nt][1] * inv0));
        *(float2*)&O[(size_t)(grow + 8) * DIM + col] =
            make_float2(to_tf32(o[nt][2] * inv1), to_tf32(o[nt][3] * inv1));
    }
}

// ---------------------------------------------------------------------------
// Launch
// ---------------------------------------------------------------------------
extern "C" void kernel_launch(void* const* d_in, const int* in_sizes, int n_in,
                              void* d_out, int out_size)
{
    const float* x     = (const float*)d_in[0];
    const float* freqs = (const float*)d_in[1];
    const float* Wq    = (const float*)d_in[2];
    const float* bq    = (const float*)d_in[3];
    const float* Wk    = (const float*)d_in[4];
    const float* bk    = (const float*)d_in[5];
    const float* Wv    = (const float*)d_in[6];
    const float* bv    = (const float*)d_in[7];
    const float* Wo    = (const float*)d_in[8];
    const float* bo    = (const float*)d_in[9];
    const float* gq    = (const float*)d_in[10];
    const float* gk    = (const float*)d_in[11];
    float* out = (float*)d_out;

    float *q, *k, *v, *attn, *xt, *wq, *wk, *wv, *wo;
    cudaGetSymbolAddress((void**)&q,    g_q);
    cudaGetSymbolAddress((void**)&k,    g_k);
    cudaGetSymbolAddress((void**)&v,    g_v);
    cudaGetSymbolAddress((void**)&attn, g_attn);
    cudaGetSymbolAddress((void**)&xt,   g_xt);
    cudaGetSymbolAddress((void**)&wq,   g_wq);
    cudaGetSymbolAddress((void**)&wk,   g_wk);
    cudaGetSymbolAddress((void**)&wv,   g_wv);
    cudaGetSymbolAddress((void**)&wo,   g_wo);

    cudaFuncSetAttribute(flash_tf32_kernel,
                         cudaFuncAttributeMaxDynamicSharedMemorySize, FA_SMEM_BYTES);
    cudaFuncSetAttribute(gemm_tf32_kernel<false>,
                         cudaFuncAttributeMaxDynamicSharedMemorySize, GEMM_SMEM_BYTES);
    cudaFuncSetAttribute(gemm_tf32_kernel<true>,
                         cudaFuncAttributeMaxDynamicSharedMemorySize, GEMM_SMEM_BYTES);

    dim3 gemm_grid(DIM / 128, SEQ / 128);   // (12, 32)

    // Prep: trig table + tf32 rounding of x and weights
    trig_kernel<<<(SEQ * 64 + 255) / 256, 256>>>(freqs);
    const int xn4 = SEQ * DIM / 4, wn4 = DIM * DIM / 4;
    round_tf32_kernel<<<(xn4 + 255) / 256, 256>>>(x,  xt, xn4);
    round_tf32_kernel<<<(wn4 + 255) / 256, 256>>>(Wq, wq, wn4);
    round_tf32_kernel<<<(wn4 + 255) / 256, 256>>>(Wk, wk, wn4);
    round_tf32_kernel<<<(wn4 + 255) / 256, 256>>>(Wv, wv, wn4);
    round_tf32_kernel<<<(wn4 + 255) / 256, 256>>>(Wo, wo, wn4);

    gemm_tf32_kernel<false><<<gemm_grid, 256, GEMM_SMEM_BYTES>>>(xt, wq, bq, q, SEQ, DIM, DIM);
    gemm_tf32_kernel<false><<<gemm_grid, 256, GEMM_SMEM_BYTES>>>(xt, wk, bk, k, SEQ, DIM, DIM);
    gemm_tf32_kernel<true ><<<gemm_grid, 256, GEMM_SMEM_BYTES>>>(xt, wv, bv, v, SEQ, DIM, DIM);

    rmsnorm_rope_kernel<<<SEQ, 256>>>(q, gq);
    rmsnorm_rope_kernel<<<SEQ, 256>>>(k, gk);

    flash_tf32_kernel<<<dim3(SEQ / 64, NHEADS), 128, FA_SMEM_BYTES>>>(q, k, v, attn);

    gemm_tf32_kernel<false><<<gemm_grid, 256, GEMM_SMEM_BYTES>>>(attn, wo, bo, out, SEQ, DIM, DIM);
}

// round 4
// speedup vs baseline: 1.0225x; 1.0225x over previous
#include <cuda_runtime.h>
#include <cuda_bf16.h>
#include <math.h>

// ---------------------------------------------------------------------------
// Problem constants (B=1, S=4096, DIM=1536, HEADS=12, HEAD_DIM=128)
// ---------------------------------------------------------------------------
#define SEQ    4096
#define DIM    1536
#define NHEADS 12
#define HDIM   128
#define EPS    1e-6f

// Scratch (allocation-free rule: __device__ globals)
__device__ float g_q[SEQ * DIM];
__device__ float g_k[SEQ * DIM];
__device__ float g_v[SEQ * DIM];
__device__ float g_attn[SEQ * DIM];
__device__ float g_trig[SEQ * 64 * 2];   // interleaved cos, sin per (pos, pair)

// ---------------------------------------------------------------------------
// Helpers
// ---------------------------------------------------------------------------
__device__ __forceinline__ float to_tf32(float x) {
    unsigned u;
    asm("cvt.rna.tf32.f32 %0, %1;" : "=r"(u) : "f"(x));
    return __uint_as_float(u);
}
__device__ __forceinline__ unsigned fu(float x) { return __float_as_uint(x); }

__device__ __forceinline__ void mma_tf32(float* d, const unsigned* a,
                                         unsigned b0, unsigned b1) {
    asm volatile(
        "mma.sync.aligned.m16n8k8.row.col.f32.tf32.tf32.f32 "
        "{%0,%1,%2,%3}, {%4,%5,%6,%7}, {%8,%9}, {%0,%1,%2,%3};\n"
        : "+f"(d[0]), "+f"(d[1]), "+f"(d[2]), "+f"(d[3])
        : "r"(a[0]), "r"(a[1]), "r"(a[2]), "r"(a[3]), "r"(b0), "r"(b1));
}

__device__ __forceinline__ void cp16(float* smem_dst, const float* gsrc) {
    unsigned s = (unsigned)__cvta_generic_to_shared(smem_dst);
    asm volatile("cp.async.cg.shared.global [%0], [%1], 16;\n" :: "r"(s), "l"(gsrc));
}
__device__ __forceinline__ void cp_commit() {
    asm volatile("cp.async.commit_group;\n");
}
template <int N>
__device__ __forceinline__ void cp_wait() {
    asm volatile("cp.async.wait_group %0;\n" :: "n"(N));
}

// ---------------------------------------------------------------------------
// RoPE trig table with double-precision range reduction.
// ---------------------------------------------------------------------------
__global__ __launch_bounds__(256) void trig_kernel(const float* __restrict__ freqs) {
    int idx = blockIdx.x * blockDim.x + threadIdx.x;
    if (idx >= SEQ * 64) return;
    double a = (double)freqs[idx];
    double s, c;
    sincos(a, &s, &c);
    g_trig[idx * 2 + 0] = (float)c;
    g_trig[idx * 2 + 1] = (float)s;
}

// ---------------------------------------------------------------------------
// tf32 tensor-core GEMM, multi-output over blockIdx.z:
//   C_z[M,N] = A[M,K] @ W_z[N,K]^T + bias_z[N]
// BM=BN=128, BK=16, 256 threads (8 warps 4m x 2n), warp tile 32x64.
// Register-prefetch double buffer (R2 structure), inline tf32 rounding.
// roundZ: tf32-round output of this z (for v feeding flash).
// ---------------------------------------------------------------------------
#define GBK     16
#define GSTRIDE 20

struct GPre { float4 a0, a1, w0, w1; };

__device__ __forceinline__ void g_store_stage(float* as, float* ws,
                                              int lrow, int lc4, const GPre& p) {
    float* d0 = &as[lrow * GSTRIDE + lc4];
    float* d1 = &as[(lrow + 64) * GSTRIDE + lc4];
    *(float4*)d0 = make_float4(to_tf32(p.a0.x), to_tf32(p.a0.y), to_tf32(p.a0.z), to_tf32(p.a0.w));
    *(float4*)d1 = make_float4(to_tf32(p.a1.x), to_tf32(p.a1.y), to_tf32(p.a1.z), to_tf32(p.a1.w));
    float* e0 = &ws[lrow * GSTRIDE + lc4];
    float* e1 = &ws[(lrow + 64) * GSTRIDE + lc4];
    *(float4*)e0 = make_float4(to_tf32(p.w0.x), to_tf32(p.w0.y), to_tf32(p.w0.z), to_tf32(p.w0.w));
    *(float4*)e1 = make_float4(to_tf32(p.w1.x), to_tf32(p.w1.y), to_tf32(p.w1.z), to_tf32(p.w1.w));
}

__global__ __launch_bounds__(256, 2) void gemm_tf32_kernel(
    const float* __restrict__ A,
    const float* __restrict__ W0, const float* __restrict__ W1, const float* __restrict__ W2,
    const float* __restrict__ b0p, const float* __restrict__ b1p, const float* __restrict__ b2p,
    float* __restrict__ C0, float* __restrict__ C1, float* __restrict__ C2,
    int roundZ, int M, int N, int K)
{
    __shared__ float As[2][128 * GSTRIDE];
    __shared__ float Ws[2][128 * GSTRIDE];

    const int z = blockIdx.z;
    const float* W    = (z == 0) ? W0  : (z == 1) ? W1  : W2;
    const float* bias = (z == 0) ? b0p : (z == 1) ? b1p : b2p;
    float* C          = (z == 0) ? C0  : (z == 1) ? C1  : C2;
    const bool doRound = (z == roundZ);

    const int t    = threadIdx.x;
    const int lane = t & 31;
    const int warp = t >> 5;
    const int wm   = warp >> 1;
    const int wn   = warp & 1;
    const int bm   = blockIdx.y * 128;
    const int bn   = blockIdx.x * 128;

    const int lrow = t >> 2;
    const int lc4  = (t & 3) * 4;

    const float* Ap = A + (size_t)(bm + lrow) * K + lc4;
    const float* Wp = W + (size_t)(bn + lrow) * K + lc4;
    const size_t rK = (size_t)64 * K;

    float c[2][8][4];
#pragma unroll
    for (int mt = 0; mt < 2; mt++)
#pragma unroll
        for (int nt = 0; nt < 8; nt++)
#pragma unroll
            for (int j = 0; j < 4; j++) c[mt][nt][j] = 0.f;

    const int KITERS = K / GBK;   // 96

    GPre p;
    p.a0 = *(const float4*)(Ap);
    p.a1 = *(const float4*)(Ap + rK);
    p.w0 = *(const float4*)(Wp);
    p.w1 = *(const float4*)(Wp + rK);
    g_store_stage(As[0], Ws[0], lrow, lc4, p);
    __syncthreads();

    const int r_a = wm * 32 + (lane >> 2);
    const int r_b = wn * 64 + (lane >> 2);
    const int kq  = lane & 3;

    for (int it = 0; it < KITERS; ++it) {
        const int cur = it & 1;
        if (it + 1 < KITERS) {
            const float* ap = Ap + (it + 1) * GBK;
            const float* wp = Wp + (it + 1) * GBK;
            p.a0 = *(const float4*)(ap);
            p.a1 = *(const float4*)(ap + rK);
            p.w0 = *(const float4*)(wp);
            p.w1 = *(const float4*)(wp + rK);
        }

        const float* as = As[cur];
        const float* ws = Ws[cur];
#pragma unroll
        for (int kt = 0; kt < 2; ++kt) {
            const int kc = kt * 8 + kq;
            unsigned a[2][4];
#pragma unroll
            for (int mt = 0; mt < 2; ++mt) {
                int r = r_a + mt * 16;
                a[mt][0] = fu(as[r * GSTRIDE + kc]);
                a[mt][1] = fu(as[(r + 8) * GSTRIDE + kc]);
                a[mt][2] = fu(as[r * GSTRIDE + kc + 4]);
                a[mt][3] = fu(as[(r + 8) * GSTRIDE + kc + 4]);
            }
#pragma unroll
            for (int nt = 0; nt < 8; ++nt) {
                int n = r_b + nt * 8;
                unsigned bb0 = fu(ws[n * GSTRIDE + kc]);
                unsigned bb1 = fu(ws[n * GSTRIDE + kc + 4]);
                mma_tf32(c[0][nt], a[0], bb0, bb1);
                mma_tf32(c[1][nt], a[1], bb0, bb1);
            }
        }

        if (it + 1 < KITERS) g_store_stage(As[cur ^ 1], Ws[cur ^ 1], lrow, lc4, p);
        __syncthreads();
    }

    // Epilogue
#pragma unroll
    for (int mt = 0; mt < 2; ++mt) {
#pragma unroll
        for (int nt = 0; nt < 8; ++nt) {
            int r0  = bm + wm * 32 + mt * 16 + (lane >> 2);
            int col = bn + wn * 64 + nt * 8 + 2 * (lane & 3);
            float bb0 = bias[col], bb1 = bias[col + 1];
            float v0 = c[mt][nt][0] + bb0, v1 = c[mt][nt][1] + bb1;
            float v2 = c[mt][nt][2] + bb0, v3 = c[mt][nt][3] + bb1;
            if (doRound) {
                v0 = to_tf32(v0); v1 = to_tf32(v1);
                v2 = to_tf32(v2); v3 = to_tf32(v3);
            }
            *(float2*)&C[(size_t)r0 * N + col]       = make_float2(v0, v1);
            *(float2*)&C[(size_t)(r0 + 8) * N + col] = make_float2(v2, v3);
        }
    }
}

// ---------------------------------------------------------------------------
// Fused RMSNorm + RoPE for q AND k in one launch: grid (SEQ, 2).
// Output tf32-rounded.
// ---------------------------------------------------------------------------
__global__ __launch_bounds__(256) void rmsnorm_rope_kernel(
    float* __restrict__ Xq, float* __restrict__ Xk,
    const float* __restrict__ gqv, const float* __restrict__ gkv)
{
    __shared__ float sh[DIM];
    __shared__ float red[8];
    __shared__ float s_r;

    const int s = blockIdx.x;
    const int which = blockIdx.y;
    float* X = which ? Xk : Xq;
    const float* g = which ? gkv : gqv;

    const int t = threadIdx.x;
    float* row = X + (size_t)s * DIM;

    float ss = 0.f;
    for (int i = t; i < DIM; i += 256) {
        float v = row[i];
        sh[i] = v;
        ss += v * v;
    }
#pragma unroll
    for (int off = 16; off > 0; off >>= 1)
        ss += __shfl_xor_sync(0xFFFFFFFFu, ss, off);
    if ((t & 31) == 0) red[t >> 5] = ss;
    __syncthreads();
    if (t == 0) {
        float tot = 0.f;
#pragma unroll
        for (int w = 0; w < 8; w++) tot += red[w];
        s_r = rsqrtf(tot / (float)DIM + EPS);
    }
    __syncthreads();
    const float r = s_r;

    for (int p = t; p < DIM / 2; p += 256) {
        int f0 = 2 * p, f1 = 2 * p + 1;
        int j = p & 63;
        float c  = g_trig[((size_t)s * 64 + j) * 2 + 0];
        float sn = g_trig[((size_t)s * 64 + j) * 2 + 1];
        float v0 = sh[f0] * r * g[f0];
        float v1 = sh[f1] * r * g[f1];
        row[f0] = to_tf32(v0 * c - v1 * sn);
        row[f1] = to_tf32(v0 * sn + v1 * c);
    }
}

// ---------------------------------------------------------------------------
// tf32 flash attention with cp.async double-buffered K/V (BK=32).
// 128 threads (4 warps), BQ=64 (16 rows/warp). Inputs pre-rounded tf32.
// ---------------------------------------------------------------------------
#define FBK       32
#define KS_STRIDE 132
#define VS_STRIDE 136
#define PS_STRIDE 36
#define FA_SMEM_FLOATS (2 * FBK * KS_STRIDE + 2 * FBK * VS_STRIDE + 64 * PS_STRIDE)
#define FA_SMEM_BYTES  (FA_SMEM_FLOATS * 4)    // 77824

__global__ __launch_bounds__(128, 2) void flash_tf32_kernel(
    const float* __restrict__ Q, const float* __restrict__ Kg,
    const float* __restrict__ Vg, float* __restrict__ O)
{
    extern __shared__ float sm[];
    float* Kb[2];
    float* Vb[2];
    Kb[0] = sm;
    Kb[1] = Kb[0] + FBK * KS_STRIDE;
    Vb[0] = Kb[1] + FBK * KS_STRIDE;
    Vb[1] = Vb[0] + FBK * VS_STRIDE;
    float* Ps = Vb[1] + FBK * VS_STRIDE;

    const int h    = blockIdx.y;
    const int qb   = blockIdx.x;
    const int t    = threadIdx.x;
    const int lane = t & 31;
    const int warp = t >> 5;
    const int r0   = lane >> 2;
    const int qc   = lane & 3;
    const float scale = 0.08838834764831845f;   // 1/sqrt(128)

    // ---- Stage Q tile (rows 0..31 -> Kb[0], 32..63 -> Kb[1]) ----
    {
        const float* src = Q + (size_t)(qb * 64) * DIM + h * HDIM;
        for (int i = t; i < 64 * 32; i += 128) {
            int r = i >> 5, c4 = (i & 31) * 4;
            float4 v = *(const float4*)&src[(size_t)r * DIM + c4];
            float* d = Kb[r >> 5] + (r & 31) * KS_STRIDE + c4;
            *(float4*)d = v;
        }
    }
    __syncthreads();

    unsigned qa[16][4];
    {
        const float* qbuf = Kb[warp >> 1];
        const int rb = (warp * 16 + r0) & 31;
#pragma unroll
        for (int kt = 0; kt < 16; ++kt) {
            int kc = kt * 8 + qc;
            qa[kt][0] = fu(qbuf[rb * KS_STRIDE + kc]);
            qa[kt][1] = fu(qbuf[(rb + 8) * KS_STRIDE + kc]);
            qa[kt][2] = fu(qbuf[rb * KS_STRIDE + kc + 4]);
            qa[kt][3] = fu(qbuf[(rb + 8) * KS_STRIDE + kc + 4]);
        }
    }
    __syncthreads();

    auto stage_kv = [&](int kb) {
        float* dk = Kb[kb & 1];
        float* dv = Vb[kb & 1];
        const float* ks = Kg + (size_t)(kb * FBK) * DIM + h * HDIM;
        const float* vs = Vg + (size_t)(kb * FBK) * DIM + h * HDIM;
        for (int i = t; i < FBK * 32; i += 128) {
            int r = i >> 5, c4 = (i & 31) * 4;
            cp16(&dk[r * KS_STRIDE + c4], &ks[(size_t)r * DIM + c4]);
            cp16(&dv[r * VS_STRIDE + c4], &vs[(size_t)r * DIM + c4]);
        }
        cp_commit();
    };

    stage_kv(0);
    stage_kv(1);

    float o[16][4];
#pragma unroll
    for (int nt = 0; nt < 16; ++nt)
#pragma unroll
        for (int j = 0; j < 4; ++j) o[nt][j] = 0.f;

    float m0 = -1e30f, m1 = -1e30f, l0 = 0.f, l1 = 0.f;
    const int prow = warp * 16 + r0;
    const int NT = SEQ / FBK;   // 128

    for (int kb = 0; kb < NT; ++kb) {
        if (kb + 1 < NT) cp_wait<1>(); else cp_wait<0>();
        __syncthreads();

        const float* Ks = Kb[kb & 1];
        const float* Vs = Vb[kb & 1];

        float s[4][4];
#pragma unroll
        for (int nt = 0; nt < 4; ++nt)
#pragma unroll
            for (int j = 0; j < 4; ++j) s[nt][j] = 0.f;

#pragma unroll
        for (int nt = 0; nt < 4; ++nt) {
            const int n = nt * 8 + r0;
#pragma unroll
            for (int kt = 0; kt < 16; ++kt) {
                int kc = kt * 8 + qc;
                unsigned b0 = fu(Ks[n * KS_STRIDE + kc]);
                unsigned b1 = fu(Ks[n * KS_STRIDE + kc + 4]);
                mma_tf32(s[nt], qa[kt], b0, b1);
            }
        }

        float mx0 = -1e30f, mx1 = -1e30f;
#pragma unroll
        for (int nt = 0; nt < 4; ++nt) {
            mx0 = fmaxf(mx0, fmaxf(s[nt][0], s[nt][1]));
            mx1 = fmaxf(mx1, fmaxf(s[nt][2], s[nt][3]));
        }
        mx0 = fmaxf(mx0, __shfl_xor_sync(0xFFFFFFFFu, mx0, 1));
        mx0 = fmaxf(mx0, __shfl_xor_sync(0xFFFFFFFFu, mx0, 2));
        mx1 = fmaxf(mx1, __shfl_xor_sync(0xFFFFFFFFu, mx1, 1));
        mx1 = fmaxf(mx1, __shfl_xor_sync(0xFFFFFFFFu, mx1, 2));

        float nm0 = fmaxf(m0, mx0 * scale);
        float nm1 = fmaxf(m1, mx1 * scale);
        float corr0 = __expf(m0 - nm0);
        float corr1 = __expf(m1 - nm1);

        float sum0 = 0.f, sum1 = 0.f;
#pragma unroll
        for (int nt = 0; nt < 4; ++nt) {
            s[nt][0] = __expf(s[nt][0] * scale - nm0);
            s[nt][1] = __expf(s[nt][1] * scale - nm0);
            s[nt][2] = __expf(s[nt][2] * scale - nm1);
            s[nt][3] = __expf(s[nt][3] * scale - nm1);
            sum0 += s[nt][0] + s[nt][1];
            sum1 += s[nt][2] + s[nt][3];
        }
        sum0 += __shfl_xor_sync(0xFFFFFFFFu, sum0, 1);
        sum0 += __shfl_xor_sync(0xFFFFFFFFu, sum0, 2);
        sum1 += __shfl_xor_sync(0xFFFFFFFFu, sum1, 1);
        sum1 += __shfl_xor_sync(0xFFFFFFFFu, sum1, 2);

        l0 = l0 * corr0 + sum0;
        l1 = l1 * corr1 + sum1;
        m0 = nm0;
        m1 = nm1;

#pragma unroll
        for (int nt = 0; nt < 16; ++nt) {
            o[nt][0] *= corr0; o[nt][1] *= corr0;
            o[nt][2] *= corr1; o[nt][3] *= corr1;
        }

#pragma unroll
        for (int nt = 0; nt < 4; ++nt) {
            int pc = nt * 8 + 2 * qc;
            *(float2*)&Ps[prow * PS_STRIDE + pc] =
                make_float2(to_tf32(s[nt][0]), to_tf32(s[nt][1]));
            *(float2*)&Ps[(prow + 8) * PS_STRIDE + pc] =
                make_float2(to_tf32(s[nt][2]), to_tf32(s[nt][3]));
        }
        __syncwarp();

#pragma unroll
        for (int kt = 0; kt < 4; ++kt) {
            unsigned a[4];
            int kc = kt * 8 + qc;
            a[0] = fu(Ps[prow * PS_STRIDE + kc]);
            a[1] = fu(Ps[(prow + 8) * PS_STRIDE + kc]);
            a[2] = fu(Ps[prow * PS_STRIDE + kc + 4]);
            a[3] = fu(Ps[(prow + 8) * PS_STRIDE + kc + 4]);
            const int vr = kc * VS_STRIDE + r0;
#pragma unroll
            for (int nt = 0; nt < 16; ++nt) {
                unsigned b0 = fu(Vs[vr + nt * 8]);
                unsigned b1 = fu(Vs[vr + nt * 8 + 4 * VS_STRIDE]);
                mma_tf32(o[nt], a, b0, b1);
            }
        }
        __syncthreads();
        if (kb + 2 < NT) stage_kv(kb + 2);
    }

    float inv0 = 1.f / l0, inv1 = 1.f / l1;
    int grow = qb * 64 + warp * 16 + r0;
#pragma unroll
    for (int nt = 0; nt < 16; ++nt) {
        int col = h * HDIM + nt * 8 + 2 * qc;
        *(float2*)&O[(size_t)grow * DIM + col] =
            make_float2(to_tf32(o[nt][0] * inv0), to_tf32(o[nt][1] * inv0));
        *(float2*)&O[(size_t)(grow + 8) * DIM + col] =
            make_float2(to_tf32(o[nt][2] * inv1), to_tf32(o[nt][3] * inv1));
    }
}

// ---------------------------------------------------------------------------
// Launch
// ---------------------------------------------------------------------------
extern "C" void kernel_launch(void* const* d_in, const int* in_sizes, int n_in,
                              void* d_out, int out_size)
{
    const float* x     = (const float*)d_in[0];
    const float* freqs = (const float*)d_in[1];
    const float* Wq    = (const float*)d_in[2];
    const float* bq    = (const float*)d_in[3];
    const float* Wk    = (const float*)d_in[4];
    const float* bk    = (const float*)d_in[5];
    const float* Wv    = (const float*)d_in[6];
    const float* bv    = (const float*)d_in[7];
    const float* Wo    = (const float*)d_in[8];
    const float* bo    = (const float*)d_in[9];
    const float* gq    = (const float*)d_in[10];
    const float* gk    = (const float*)d_in[11];
    float* out = (float*)d_out;

    float *q, *k, *v, *attn;
    cudaGetSymbolAddress((void**)&q,    g_q);
    cudaGetSymbolAddress((void**)&k,    g_k);
    cudaGetSymbolAddress((void**)&v,    g_v);
    cudaGetSymbolAddress((void**)&attn, g_attn);

    cudaFuncSetAttribute(flash_tf32_kernel,
                         cudaFuncAttributeMaxDynamicSharedMemorySize, FA_SMEM_BYTES);

    trig_kernel<<<(SEQ * 64 + 255) / 256, 256>>>(freqs);

    // Fused Q/K/V projection: one launch, 1152 CTAs (4 full-ish waves @ 2/SM).
    dim3 qkv_grid(DIM / 128, SEQ / 128, 3);
    gemm_tf32_kernel<<<qkv_grid, 256>>>(
        x, Wq, Wk, Wv, bq, bk, bv, q, k, v,
        /*roundZ=*/2, SEQ, DIM, DIM);

    // RMSNorm+RoPE for q and k in one launch.
    rmsnorm_rope_kernel<<<dim3(SEQ, 2), 256>>>(q, k, gq, gk);

    flash_tf32_kernel<<<dim3(SEQ / 64, NHEADS), 128, FA_SMEM_BYTES>>>(q, k, v, attn);

    // Output projection (z = 0 only, no rounding).
    dim3 o_grid(DIM / 128, SEQ / 128, 1);
    gemm_tf32_kernel<<<o_grid, 256>>>(
        attn, Wo, Wo, Wo, bo, bo, bo, out, out, out,
        /*roundZ=*/-1, SEQ, DIM, DIM);
}